// round 12
// baseline (speedup 1.0000x reference)
#include <cuda_runtime.h>
#include <cuda_fp16.h>

#define B_SZ 4096
#define T_SZ 2048
#define NGROUPS 512
typedef unsigned u32;

__device__ int g_counter;
__device__ int g_order[B_SZ];

// ---------------- prologue: counting sort by descending length --------------------
__global__ __launch_bounds__(1024)
void sort_kernel(const int* __restrict__ lengths)
{
    __shared__ int hist[2048];
    const int tid = threadIdx.x;
    hist[tid] = 0; hist[tid + 1024] = 0;
    __syncthreads();
    for (int i = tid; i < B_SZ; i += 1024)
        atomicAdd(&hist[T_SZ - lengths[i]], 1);
    __syncthreads();
    const int o0 = hist[tid], o1 = hist[tid + 1024];
    for (int off = 1; off < 2048; off <<= 1) {
        int v0 = hist[tid]        + ((tid        >= off) ? hist[tid - off]        : 0);
        int v1 = hist[tid + 1024] + ((tid + 1024 >= off) ? hist[tid + 1024 - off] : 0);
        __syncthreads();
        hist[tid] = v0; hist[tid + 1024] = v1;
        __syncthreads();
    }
    hist[tid] -= o0; hist[tid + 1024] -= o1;
    __syncthreads();
    for (int i = tid; i < B_SZ; i += 1024) {
        int pos = atomicAdd(&hist[T_SZ - lengths[i]], 1);
        g_order[pos] = i;
    }
    if (tid == 0) g_counter = 0;
}

// ---------------- helpers ---------------------------------------------------------
__device__ __forceinline__ float fast_ex2(float x) {
    float r; asm("ex2.approx.f32 %0, %1;" : "=f"(r) : "f"(x)); return r;
}
__device__ __forceinline__ float fast_rcp(float x) {
    float r; asm("rcp.approx.f32 %0, %1;" : "=f"(r) : "f"(x)); return r;
}
__device__ __forceinline__ float sigmoid_(float x) {
    return fast_rcp(1.0f + fast_ex2(-1.44269504f * x));
}
__device__ __forceinline__ u32 tanh2(u32 a) {          // dual f16 tanh, 1 MUFU
    u32 d; asm("tanh.approx.f16x2 %0, %1;" : "=r"(d) : "r"(a)); return d;
}
__device__ __forceinline__ u32 f2h2(float lo, float hi) {
    __half2 h = __floats2half2_rn(lo, hi);             // .x = lo, .y = hi
    return *reinterpret_cast<u32*>(&h);
}
__device__ __forceinline__ __half2 h2(u32 a) { return *reinterpret_cast<__half2*>(&a); }
__device__ __forceinline__ u32 u2(__half2 a) { return *reinterpret_cast<u32*>(&a); }
__device__ __forceinline__ u32 movm_t(u32 a) {         // 8x8 b16 register transpose
    u32 d; asm("movmatrix.sync.aligned.m8n8.trans.b16 %0, %1;" : "=r"(d) : "r"(a));
    return d;
}
// D = A(16x16 f16,row) * B(16x8 f16,col) + D   (fp32 accum)
__device__ __forceinline__ void mma16816(float& d0, float& d1, float& d2, float& d3,
                                         u32 a0, u32 a1, u32 a2, u32 a3,
                                         u32 b0, u32 b1) {
    asm volatile(
        "mma.sync.aligned.m16n8k16.row.col.f32.f16.f16.f32 "
        "{%0,%1,%2,%3},{%4,%5,%6,%7},{%8,%9},{%0,%1,%2,%3};"
        : "+f"(d0), "+f"(d1), "+f"(d2), "+f"(d3)
        : "r"(a0), "r"(a1), "r"(a2), "r"(a3), "r"(b0), "r"(b1));
}

// ---------------- main kernel: 8 seqs/warp, HMMA + movmatrix + f16x2 tanh ---------
// Gates G(128x8) = W_hh_s(128x32) h(32x8) with D-init = x*w_ih_s + bias_s (FFMA).
// h carried as 4 half2 regs (pair = 2 seqs), transposed per step via movmatrix.
// Scales folded into weights: 0.5 for i,f,o (sigma(v) = 0.5 + 0.5 tanh(v/2)).
__global__ __launch_bounds__(128)
void bilstm_mma_kernel(const float* __restrict__ x,
                       const int* __restrict__ lengths,
                       const float* __restrict__ w_ih,
                       const float* __restrict__ w_hh,
                       const float* __restrict__ b_ih,
                       const float* __restrict__ b_hh,
                       const float* __restrict__ fc_w,
                       const float* __restrict__ fc_b,
                       const float* __restrict__ fc2_w,
                       const float* __restrict__ fc2_b,
                       float* __restrict__ out)
{
    const int lane = threadIdx.x & 31;
    const int wid  = threadIdx.x >> 5;
    const int g4 = lane >> 2;        // 0..7
    const int tq = lane & 3;         // 0..3

    // per-warp x chunk, f32, padded stride 33 (conflict-free 4-address LDS)
    __shared__ float xsh[4][8 * 33];
    float* xS = xsh[wid];

    // ---- weights, loaded once ----
    const float scl[4] = {0.5f, 0.5f, 1.0f, 0.5f};
    u32 Afr[8][2][4];
    float wihR[16], biasR[16];       // [mt*2 + rh], rows 32g+16bb+8rh+g4
#pragma unroll
    for (int mt = 0; mt < 8; ++mt) {
        const int g = mt >> 1, bb = mt & 1;
        const float s = scl[g];
        const int R0 = g * 32 + bb * 16 + g4;
        const int R1 = R0 + 8;
#pragma unroll
        for (int kt = 0; kt < 2; ++kt) {
            const int c0 = kt * 16 + 2 * tq;
            Afr[mt][kt][0] = f2h2(s * __ldg(w_hh + R0 * 32 + c0),
                                  s * __ldg(w_hh + R0 * 32 + c0 + 1));
            Afr[mt][kt][1] = f2h2(s * __ldg(w_hh + R1 * 32 + c0),
                                  s * __ldg(w_hh + R1 * 32 + c0 + 1));
            Afr[mt][kt][2] = f2h2(s * __ldg(w_hh + R0 * 32 + c0 + 8),
                                  s * __ldg(w_hh + R0 * 32 + c0 + 9));
            Afr[mt][kt][3] = f2h2(s * __ldg(w_hh + R1 * 32 + c0 + 8),
                                  s * __ldg(w_hh + R1 * 32 + c0 + 9));
        }
        wihR[mt * 2 + 0] = s * __ldg(w_ih + R0);
        wihR[mt * 2 + 1] = s * __ldg(w_ih + R1);
        biasR[mt * 2 + 0] = s * (__ldg(b_ih + R0) + __ldg(b_hh + R0));
        biasR[mt * 2 + 1] = s * (__ldg(b_ih + R1) + __ldg(b_hh + R1));
    }

    const unsigned FULL = 0xffffffffu;
    const __half2 h05 = __floats2half2_rn(0.5f, 0.5f);

    for (;;) {
        int s0 = 0;
        if (lane == 0) s0 = atomicAdd(&g_counter, 1);
        s0 = __shfl_sync(FULL, s0, 0);
        if (s0 >= NGROUPS) break;

        int idxs[8];
#pragma unroll
        for (int r = 0; r < 8; ++r) idxs[r] = g_order[s0 * 8 + r];
        const int lenmax = __ldg(lengths + idxs[0]);          // sorted desc
        const int lenA = __ldg(lengths + idxs[2 * tq]);       // seq 2tq
        const int lenB = __ldg(lengths + idxs[2 * tq + 1]);   // seq 2tq+1

        // state: pair p = bb*2 + rh holds (seq 2tq, seq 2tq+1) as half2 in hp[p];
        // c kept in f32: c[2p + sh]. hidden j = 16bb + g4 + 8rh.
        u32 hp[4] = {0u, 0u, 0u, 0u};
        float cS[8];
#pragma unroll
        for (int st = 0; st < 8; ++st) cS[st] = 0.0f;

        const int tmax = lenmax - 1;
        const int ctop = tmax >> 5;

#pragma unroll 1
        for (int c = ctop; c >= 0; --c) {
            __syncwarp();
#pragma unroll
            for (int r = 0; r < 8; ++r)
                xS[r * 33 + lane] = __ldg(x + (size_t)idxs[r] * T_SZ + (c << 5) + lane);
            __syncwarp();

            const int istart = (c == ctop) ? (tmax & 31) : 31;
#pragma unroll 2
            for (int i = istart; i >= 0; --i) {
                const int t = (c << 5) + i;
                const bool m0 = t < lenA;
                const bool m1 = t < lenB;
                const u32 msk = (m0 ? 0x0000FFFFu : 0u) | (m1 ? 0xFFFF0000u : 0u);

                const float x0 = xS[(2 * tq) * 33 + i];
                const float x1 = xS[(2 * tq + 1) * 33 + i];

                // B fragments: register-space transpose of h pairs
                const u32 b00 = movm_t(hp[0]);   // j 0..7
                const u32 b01 = movm_t(hp[1]);   // j 8..15
                const u32 b10 = movm_t(hp[2]);   // j 16..23
                const u32 b11 = movm_t(hp[3]);   // j 24..31

                // D init = x * w_ih_s + bias_s  (fma pipe; replaces 3rd MMA)
                float d[8][4];
#pragma unroll
                for (int mt = 0; mt < 8; ++mt) {
#pragma unroll
                    for (int rh = 0; rh < 2; ++rh) {
                        d[mt][2 * rh + 0] = fmaf(x0, wihR[mt * 2 + rh], biasR[mt * 2 + rh]);
                        d[mt][2 * rh + 1] = fmaf(x1, wihR[mt * 2 + rh], biasR[mt * 2 + rh]);
                    }
                }

                // activation for pair p given its 4 gate D-tiles
                auto act_pair = [&](int p, const float* di, const float* df,
                                    const float* dg, const float* dO) {
                    const int rh = p & 1;
                    const int dr = 2 * rh;
                    const u32 Ti = tanh2(f2h2(di[dr], di[dr + 1]));
                    const u32 Tf = tanh2(f2h2(df[dr], df[dr + 1]));
                    const u32 Tg = tanh2(f2h2(dg[dr], dg[dr + 1]));
                    const u32 To = tanh2(f2h2(dO[dr], dO[dr + 1]));
                    const __half2 I2 = __hfma2(h05, h2(Ti), h05);       // sigmoid
                    const float2 IG = __half22float2(__hmul2(I2, h2(Tg)));
                    const float2 Ff = __half22float2(h2(Tf));
                    const float cn0 = fmaf(fmaf(0.5f, Ff.x, 0.5f), cS[2 * p],     IG.x);
                    const float cn1 = fmaf(fmaf(0.5f, Ff.y, 0.5f), cS[2 * p + 1], IG.y);
                    const u32 Tc = tanh2(f2h2(cn0, cn1));
                    const __half2 O2 = __hfma2(h05, h2(To), h05);
                    const u32 hn = u2(__hmul2(O2, h2(Tc)));
                    hp[p] = (hn & msk) | (hp[p] & ~msk);
                    cS[2 * p]     = m0 ? cn0 : cS[2 * p];
                    cS[2 * p + 1] = m1 ? cn1 : cS[2 * p + 1];
                };

                // bb = 0 tiles (mt even): 8 MMAs
#pragma unroll
                for (int mt = 0; mt < 8; mt += 2) {
                    mma16816(d[mt][0], d[mt][1], d[mt][2], d[mt][3],
                             Afr[mt][0][0], Afr[mt][0][1], Afr[mt][0][2], Afr[mt][0][3],
                             b00, b01);
                    mma16816(d[mt][0], d[mt][1], d[mt][2], d[mt][3],
                             Afr[mt][1][0], Afr[mt][1][1], Afr[mt][1][2], Afr[mt][1][3],
                             b10, b11);
                }
                act_pair(0, d[0], d[2], d[4], d[6]);
                act_pair(1, d[0], d[2], d[4], d[6]);

                // bb = 1 tiles (mt odd): 8 MMAs (issue overlaps bb=0 activations)
#pragma unroll
                for (int mt = 1; mt < 8; mt += 2) {
                    mma16816(d[mt][0], d[mt][1], d[mt][2], d[mt][3],
                             Afr[mt][0][0], Afr[mt][0][1], Afr[mt][0][2], Afr[mt][0][3],
                             b00, b01);
                    mma16816(d[mt][0], d[mt][1], d[mt][2], d[mt][3],
                             Afr[mt][1][0], Afr[mt][1][1], Afr[mt][1][2], Afr[mt][1][3],
                             b10, b11);
                }
                act_pair(2, d[1], d[3], d[5], d[7]);
                act_pair(3, d[1], d[3], d[5], d[7]);
            }
        }

        // ---- FC head: sigmoid(fc2(elu(fc1(h_n)))) for the 8 group sequences ----
        __syncwarp();
#pragma unroll
        for (int p = 0; p < 4; ++p) {                 // hf[seq*33 + j] reuses xS
            const int bb = p >> 1, rh = p & 1;
            const float2 v = __half22float2(h2(hp[p]));
            xS[(2 * tq) * 33     + 16 * bb + g4 + 8 * rh] = v.x;
            xS[(2 * tq + 1) * 33 + 16 * bb + g4 + 8 * rh] = v.y;
        }
        __syncwarp();

#pragma unroll 1
        for (int s = 0; s < 8; ++s) {
            float o1 = __ldg(fc_b + lane);
            float o2 = __ldg(fc_b + lane + 32);
#pragma unroll
            for (int k = 0; k < 32; ++k) {
                const float hk = xS[s * 33 + k];
                o1 = fmaf(hk, __ldg(fc_w + lane * 32 + k), o1);
                o2 = fmaf(hk, __ldg(fc_w + (lane + 32) * 32 + k), o2);
            }
            o1 = (o1 > 0.0f) ? o1 : (fast_ex2(1.44269504f * o1) - 1.0f);
            o2 = (o2 > 0.0f) ? o2 : (fast_ex2(1.44269504f * o2) - 1.0f);
            float part = o1 * __ldg(fc2_w + lane) + o2 * __ldg(fc2_w + lane + 32);
#pragma unroll
            for (int dd = 16; dd >= 1; dd >>= 1)
                part += __shfl_xor_sync(FULL, part, dd);
            if (lane == 0)
                out[idxs[s]] = sigmoid_(part + __ldg(fc2_b));
        }
        __syncwarp();      // head reads done before next group's x staging
    }
}

extern "C" void kernel_launch(void* const* d_in, const int* in_sizes, int n_in,
                              void* d_out, int out_size)
{
    const float* x       = (const float*)d_in[0];
    const int*   lengths = (const int*)  d_in[1];
    const float* w_ih    = (const float*)d_in[2];
    const float* w_hh    = (const float*)d_in[3];
    const float* b_ih    = (const float*)d_in[4];
    const float* b_hh    = (const float*)d_in[5];
    const float* fc_w    = (const float*)d_in[6];
    const float* fc_b    = (const float*)d_in[7];
    const float* fc2_w   = (const float*)d_in[8];
    const float* fc2_b   = (const float*)d_in[9];
    float* out = (float*)d_out;

    sort_kernel<<<1, 1024>>>(lengths);
    // 148 blocks x 4 warps = 1 warp/SMSP; atomic queue over 512 LPT-sorted
    // 8-seq groups (592 warps > 512 groups: each warp runs at most one).
    bilstm_mma_kernel<<<148, 128>>>(x, lengths, w_ih, w_hh, b_ih, b_hh,
                                    fc_w, fc_b, fc2_w, fc2_b, out);
}

// round 14
// speedup vs baseline: 1.4684x; 1.4684x over previous
#include <cuda_runtime.h>
#include <cuda_fp16.h>

#define B_SZ 4096
#define T_SZ 2048
#define NGROUPS 512
typedef unsigned u32;

__device__ int g_counter;
__device__ int g_order[B_SZ];

// ---------------- prologue: counting sort by descending length --------------------
__global__ __launch_bounds__(1024)
void sort_kernel(const int* __restrict__ lengths)
{
    __shared__ int hist[2048];
    const int tid = threadIdx.x;
    hist[tid] = 0; hist[tid + 1024] = 0;
    __syncthreads();
    for (int i = tid; i < B_SZ; i += 1024)
        atomicAdd(&hist[T_SZ - lengths[i]], 1);
    __syncthreads();
    const int o0 = hist[tid], o1 = hist[tid + 1024];
    for (int off = 1; off < 2048; off <<= 1) {
        int v0 = hist[tid]        + ((tid        >= off) ? hist[tid - off]        : 0);
        int v1 = hist[tid + 1024] + ((tid + 1024 >= off) ? hist[tid + 1024 - off] : 0);
        __syncthreads();
        hist[tid] = v0; hist[tid + 1024] = v1;
        __syncthreads();
    }
    hist[tid] -= o0; hist[tid + 1024] -= o1;
    __syncthreads();
    for (int i = tid; i < B_SZ; i += 1024) {
        int pos = atomicAdd(&hist[T_SZ - lengths[i]], 1);
        g_order[pos] = i;
    }
    if (tid == 0) g_counter = 0;
}

// ---------------- helpers ---------------------------------------------------------
__device__ __forceinline__ float fast_ex2(float x) {
    float r; asm("ex2.approx.f32 %0, %1;" : "=f"(r) : "f"(x)); return r;
}
__device__ __forceinline__ float fast_rcp(float x) {
    float r; asm("rcp.approx.f32 %0, %1;" : "=f"(r) : "f"(x)); return r;
}
__device__ __forceinline__ float sigmoid_(float x) {
    return fast_rcp(1.0f + fast_ex2(-1.44269504f * x));
}
__device__ __forceinline__ u32 tanh2(u32 a) {          // dual f16 tanh, 1 MUFU op
    u32 d; asm("tanh.approx.f16x2 %0, %1;" : "=r"(d) : "r"(a)); return d;
}
__device__ __forceinline__ u32 f2h2(float lo, float hi) {
    __half2 h = __floats2half2_rn(lo, hi);             // .x = lo, .y = hi
    return *reinterpret_cast<u32*>(&h);
}
__device__ __forceinline__ __half2 h2(u32 a) { return *reinterpret_cast<__half2*>(&a); }
__device__ __forceinline__ u32 movm_t(u32 a) {         // 8x8 b16 register transpose
    u32 d; asm("movmatrix.sync.aligned.m8n8.trans.b16 %0, %1;" : "=r"(d) : "r"(a));
    return d;
}
// D = A(16x16 f16,row) * B(16x8 f16,col) + D   (fp32 accum)
__device__ __forceinline__ void mma16816(float& d0, float& d1, float& d2, float& d3,
                                         u32 a0, u32 a1, u32 a2, u32 a3,
                                         u32 b0, u32 b1) {
    asm volatile(
        "mma.sync.aligned.m16n8k16.row.col.f32.f16.f16.f32 "
        "{%0,%1,%2,%3},{%4,%5,%6,%7},{%8,%9},{%0,%1,%2,%3};"
        : "+f"(d0), "+f"(d1), "+f"(d2), "+f"(d3)
        : "r"(a0), "r"(a1), "r"(a2), "r"(a3), "r"(b0), "r"(b1));
}

// ---------------- main kernel: 8 seqs/warp, HMMA + movmatrix ----------------------
// Identical to the 580us kernel except the activation block: gate tanh runs as
// paired tanh.approx.f16x2 (20 MUFU/step instead of 40); c and masking stay f32.
// W_ext(128x48) f16 in regs; H_ext = [h(32); x; 1]; scales folded (0.5 for i,f,o).
__global__ __launch_bounds__(128)
void bilstm_mma_kernel(const float* __restrict__ x,
                       const int* __restrict__ lengths,
                       const float* __restrict__ w_ih,
                       const float* __restrict__ w_hh,
                       const float* __restrict__ b_ih,
                       const float* __restrict__ b_hh,
                       const float* __restrict__ fc_w,
                       const float* __restrict__ fc_b,
                       const float* __restrict__ fc2_w,
                       const float* __restrict__ fc2_b,
                       float* __restrict__ out)
{
    const int lane = threadIdx.x & 31;
    const int wid  = threadIdx.x >> 5;
    const int g4 = lane >> 2;        // 0..7
    const int tq = lane & 3;         // 0..3

    // per-warp x chunk: packed (x, 1.0) halves, 8 seqs x 32 steps
    __shared__ u32 xpsh[4][8 * 32];
    u32* xpkS = xpsh[wid];

    // ---- A fragments (weights), loaded once ----
    const float scl[4] = {0.5f, 0.5f, 1.0f, 0.5f};
    u32 Afr[8][2][4];
    u32 A2f[8][2];
#pragma unroll
    for (int mt = 0; mt < 8; ++mt) {
        const int g = mt >> 1, bb = mt & 1;
        const float s = scl[g];
        const int R0 = g * 32 + bb * 16 + g4;
        const int R1 = R0 + 8;
#pragma unroll
        for (int kt = 0; kt < 2; ++kt) {
            const int c0 = kt * 16 + 2 * tq;
            Afr[mt][kt][0] = f2h2(s * __ldg(w_hh + R0 * 32 + c0),
                                  s * __ldg(w_hh + R0 * 32 + c0 + 1));
            Afr[mt][kt][1] = f2h2(s * __ldg(w_hh + R1 * 32 + c0),
                                  s * __ldg(w_hh + R1 * 32 + c0 + 1));
            Afr[mt][kt][2] = f2h2(s * __ldg(w_hh + R0 * 32 + c0 + 8),
                                  s * __ldg(w_hh + R0 * 32 + c0 + 9));
            Afr[mt][kt][3] = f2h2(s * __ldg(w_hh + R1 * 32 + c0 + 8),
                                  s * __ldg(w_hh + R1 * 32 + c0 + 9));
        }
        if (tq == 0) {   // k-tile 2: col 32 = w_ih, col 33 = fused bias
            A2f[mt][0] = f2h2(s * __ldg(w_ih + R0),
                              s * (__ldg(b_ih + R0) + __ldg(b_hh + R0)));
            A2f[mt][1] = f2h2(s * __ldg(w_ih + R1),
                              s * (__ldg(b_ih + R1) + __ldg(b_hh + R1)));
        } else { A2f[mt][0] = 0u; A2f[mt][1] = 0u; }
    }

    const unsigned FULL = 0xffffffffu;
    const __half2 h05 = __floats2half2_rn(0.5f, 0.5f);

    // ---- persistent work queue over sorted 8-seq groups ----
    for (;;) {
        int s0 = 0;
        if (lane == 0) s0 = atomicAdd(&g_counter, 1);
        s0 = __shfl_sync(FULL, s0, 0);
        if (s0 >= NGROUPS) break;

        int idxs[8];
#pragma unroll
        for (int r = 0; r < 8; ++r) idxs[r] = g_order[s0 * 8 + r];
        const int lenmax = __ldg(lengths + idxs[0]);          // sorted desc
        const int lenA = __ldg(lengths + idxs[2 * tq]);       // seq 2tq
        const int lenB = __ldg(lengths + idxs[2 * tq + 1]);   // seq 2tq+1

        // states: st = bb*4 + rh*2 + sh -> seq 2tq+sh, hidden j = 16bb + g4 + 8rh
        float hS[8], cS[8];
#pragma unroll
        for (int st = 0; st < 8; ++st) { hS[st] = 0.0f; cS[st] = 0.0f; }

        const int tmax = lenmax - 1;
        const int ctop = tmax >> 5;

        // paired activation: states st, st+1 (same bb, rh; sh = 0,1).
        // Gate args pre-scaled: 0.5 for i,f,o; 1.0 for g. 5 MUFU per pair.
        auto act_pair = [&](float di0, float di1, float df0, float df1,
                            float dg0, float dg1, float do0, float do1,
                            int st, bool m0, bool m1) {
            const u32 Ti = tanh2(f2h2(di0, di1));
            const u32 Tf = tanh2(f2h2(df0, df1));
            const u32 Tg = tanh2(f2h2(dg0, dg1));
            const u32 To = tanh2(f2h2(do0, do1));
            const __half2 I2 = __hfma2(h05, h2(Ti), h05);     // sigmoid(raw_i)
            const __half2 F2 = __hfma2(h05, h2(Tf), h05);
            const __half2 O2 = __hfma2(h05, h2(To), h05);
            const float2 IG = __half22float2(__hmul2(I2, h2(Tg)));
            const float2 Ff = __half22float2(F2);
            const float cn0 = fmaf(Ff.x, cS[st],     IG.x);
            const float cn1 = fmaf(Ff.y, cS[st + 1], IG.y);
            const u32 Tc = tanh2(f2h2(cn0, cn1));
            const float2 hn = __half22float2(__hmul2(O2, h2(Tc)));
            cS[st]     = m0 ? cn0 : cS[st];
            cS[st + 1] = m1 ? cn1 : cS[st + 1];
            hS[st]     = m0 ? hn.x : hS[st];
            hS[st + 1] = m1 ? hn.y : hS[st + 1];
        };

#pragma unroll 1
        for (int c = ctop; c >= 0; --c) {
            __syncwarp();             // prior chunk's x reads done
#pragma unroll
            for (int r = 0; r < 8; ++r) {
                const float v = __ldg(x + (size_t)idxs[r] * T_SZ + (c << 5) + lane);
                xpkS[r * 32 + lane] = f2h2(v, 1.0f);
            }
            __syncwarp();

            const int istart = (c == ctop) ? (tmax & 31) : 31;
#pragma unroll 2
            for (int i = istart; i >= 0; --i) {
                const int t = (c << 5) + i;
                const bool m0 = t < lenA;
                const bool m1 = t < lenB;

                // B fragments: register-space transpose of h (no smem)
                const u32 b00 = movm_t(f2h2(hS[0], hS[1]));   // j 0..7
                const u32 b01 = movm_t(f2h2(hS[2], hS[3]));   // j 8..15
                const u32 b10 = movm_t(f2h2(hS[4], hS[5]));   // j 16..23
                const u32 b11 = movm_t(f2h2(hS[6], hS[7]));   // j 24..31
                const u32 xv  = xpkS[g4 * 32 + i];
                const u32 b20 = (tq == 0) ? xv : 0u;

                float d[8][4];
#pragma unroll
                for (int mt = 0; mt < 8; ++mt) {
                    d[mt][0] = 0.0f; d[mt][1] = 0.0f;
                    d[mt][2] = 0.0f; d[mt][3] = 0.0f;
                }

                // bb = 0 m-tiles (mt even): 12 MMAs
#pragma unroll
                for (int mt = 0; mt < 8; mt += 2) {
                    mma16816(d[mt][0], d[mt][1], d[mt][2], d[mt][3],
                             Afr[mt][0][0], Afr[mt][0][1], Afr[mt][0][2], Afr[mt][0][3],
                             b00, b01);
                    mma16816(d[mt][0], d[mt][1], d[mt][2], d[mt][3],
                             Afr[mt][1][0], Afr[mt][1][1], Afr[mt][1][2], Afr[mt][1][3],
                             b10, b11);
                    mma16816(d[mt][0], d[mt][1], d[mt][2], d[mt][3],
                             A2f[mt][0], A2f[mt][1], 0u, 0u, b20, 0u);
                }

                // activate bb=0 state pairs (overlaps bb=1 MMA issue below)
                act_pair(d[0][0], d[0][1], d[2][0], d[2][1],
                         d[4][0], d[4][1], d[6][0], d[6][1], 0, m0, m1);
                act_pair(d[0][2], d[0][3], d[2][2], d[2][3],
                         d[4][2], d[4][3], d[6][2], d[6][3], 2, m0, m1);

                // bb = 1 m-tiles (mt odd): 12 MMAs
#pragma unroll
                for (int mt = 1; mt < 8; mt += 2) {
                    mma16816(d[mt][0], d[mt][1], d[mt][2], d[mt][3],
                             Afr[mt][0][0], Afr[mt][0][1], Afr[mt][0][2], Afr[mt][0][3],
                             b00, b01);
                    mma16816(d[mt][0], d[mt][1], d[mt][2], d[mt][3],
                             Afr[mt][1][0], Afr[mt][1][1], Afr[mt][1][2], Afr[mt][1][3],
                             b10, b11);
                    mma16816(d[mt][0], d[mt][1], d[mt][2], d[mt][3],
                             A2f[mt][0], A2f[mt][1], 0u, 0u, b20, 0u);
                }

                act_pair(d[1][0], d[1][1], d[3][0], d[3][1],
                         d[5][0], d[5][1], d[7][0], d[7][1], 4, m0, m1);
                act_pair(d[1][2], d[1][3], d[3][2], d[3][3],
                         d[5][2], d[5][3], d[7][2], d[7][3], 6, m0, m1);
            }
        }

        // ---- FC head: sigmoid(fc2(elu(fc1(h_n)))) for the 8 group sequences ----
        float* hf = reinterpret_cast<float*>(xpkS);   // reuse x buffer: hf[s*32+j]
        __syncwarp();
#pragma unroll
        for (int st = 0; st < 8; ++st) {
            const int sh = st & 1, rh = (st >> 1) & 1, bb = st >> 2;
            hf[(2 * tq + sh) * 32 + 16 * bb + g4 + 8 * rh] = hS[st];
        }
        __syncwarp();

#pragma unroll 1
        for (int s = 0; s < 8; ++s) {
            float o1 = __ldg(fc_b + lane);
            float o2 = __ldg(fc_b + lane + 32);
#pragma unroll
            for (int k = 0; k < 32; ++k) {
                const float hk = hf[s * 32 + k];
                o1 = fmaf(hk, __ldg(fc_w + lane * 32 + k), o1);
                o2 = fmaf(hk, __ldg(fc_w + (lane + 32) * 32 + k), o2);
            }
            o1 = (o1 > 0.0f) ? o1 : (fast_ex2(1.44269504f * o1) - 1.0f);
            o2 = (o2 > 0.0f) ? o2 : (fast_ex2(1.44269504f * o2) - 1.0f);
            float part = o1 * __ldg(fc2_w + lane) + o2 * __ldg(fc2_w + lane + 32);
#pragma unroll
            for (int dd = 16; dd >= 1; dd >>= 1)
                part += __shfl_xor_sync(FULL, part, dd);
            if (lane == 0)
                out[idxs[s]] = sigmoid_(part + __ldg(fc2_b));
        }
        __syncwarp();      // head reads done before next group's x staging
    }
}

extern "C" void kernel_launch(void* const* d_in, const int* in_sizes, int n_in,
                              void* d_out, int out_size)
{
    const float* x       = (const float*)d_in[0];
    const int*   lengths = (const int*)  d_in[1];
    const float* w_ih    = (const float*)d_in[2];
    const float* w_hh    = (const float*)d_in[3];
    const float* b_ih    = (const float*)d_in[4];
    const float* b_hh    = (const float*)d_in[5];
    const float* fc_w    = (const float*)d_in[6];
    const float* fc_b    = (const float*)d_in[7];
    const float* fc2_w   = (const float*)d_in[8];
    const float* fc2_b   = (const float*)d_in[9];
    float* out = (float*)d_out;

    sort_kernel<<<1, 1024>>>(lengths);
    // 148 blocks x 4 warps = 1 warp/SMSP; atomic queue over 512 LPT-sorted
    // 8-seq groups (592 warps > 512 groups: each warp runs at most one).
    bilstm_mma_kernel<<<148, 128>>>(x, lengths, w_ih, w_hh, b_ih, b_hh,
                                    fc_w, fc_b, fc2_w, fc2_b, out);
}

// round 15
// speedup vs baseline: 1.6540x; 1.1264x over previous
#include <cuda_runtime.h>
#include <cuda_fp16.h>

#define B_SZ 4096
#define T_SZ 2048
#define NGROUPS 512
typedef unsigned u32;

__device__ int g_counter;
__device__ int g_order[B_SZ];

// ---------------- prologue: counting sort by descending length --------------------
__global__ __launch_bounds__(1024)
void sort_kernel(const int* __restrict__ lengths)
{
    __shared__ int hist[2048];
    const int tid = threadIdx.x;
    hist[tid] = 0; hist[tid + 1024] = 0;
    __syncthreads();
    for (int i = tid; i < B_SZ; i += 1024)
        atomicAdd(&hist[T_SZ - lengths[i]], 1);
    __syncthreads();
    const int o0 = hist[tid], o1 = hist[tid + 1024];
    for (int off = 1; off < 2048; off <<= 1) {
        int v0 = hist[tid]        + ((tid        >= off) ? hist[tid - off]        : 0);
        int v1 = hist[tid + 1024] + ((tid + 1024 >= off) ? hist[tid + 1024 - off] : 0);
        __syncthreads();
        hist[tid] = v0; hist[tid + 1024] = v1;
        __syncthreads();
    }
    hist[tid] -= o0; hist[tid + 1024] -= o1;
    __syncthreads();
    for (int i = tid; i < B_SZ; i += 1024) {
        int pos = atomicAdd(&hist[T_SZ - lengths[i]], 1);
        g_order[pos] = i;
    }
    if (tid == 0) g_counter = 0;
}

// ---------------- helpers ---------------------------------------------------------
__device__ __forceinline__ float fast_ex2(float x) {
    float r; asm("ex2.approx.f32 %0, %1;" : "=f"(r) : "f"(x)); return r;
}
__device__ __forceinline__ float fast_rcp(float x) {
    float r; asm("rcp.approx.f32 %0, %1;" : "=f"(r) : "f"(x)); return r;
}
__device__ __forceinline__ float fast_tanh(float x) {
    float r; asm("tanh.approx.f32 %0, %1;" : "=f"(r) : "f"(x)); return r;
}
__device__ __forceinline__ float sigmoid_(float x) {
    return fast_rcp(1.0f + fast_ex2(-1.44269504f * x));
}
__device__ __forceinline__ u32 f2h2(float lo, float hi) {
    __half2 h = __floats2half2_rn(lo, hi);             // .x = lo, .y = hi
    return *reinterpret_cast<u32*>(&h);
}
__device__ __forceinline__ u32 movm_t(u32 a) {         // 8x8 b16 register transpose
    u32 d; asm("movmatrix.sync.aligned.m8n8.trans.b16 %0, %1;" : "=r"(d) : "r"(a));
    return d;
}
// D += A(16x16 f16,row) * B(16x8 f16,col)   (fp32 accum)
__device__ __forceinline__ void mma16816(float& d0, float& d1, float& d2, float& d3,
                                         u32 a0, u32 a1, u32 a2, u32 a3,
                                         u32 b0, u32 b1) {
    asm volatile(
        "mma.sync.aligned.m16n8k16.row.col.f32.f16.f16.f32 "
        "{%0,%1,%2,%3},{%4,%5,%6,%7},{%8,%9},{%0,%1,%2,%3};"
        : "+f"(d0), "+f"(d1), "+f"(d2), "+f"(d3)
        : "r"(a0), "r"(a1), "r"(a2), "r"(a3), "r"(b0), "r"(b1));
}
// D = A*B + 0 : zero C operand (no accumulator MOV-init needed)
__device__ __forceinline__ void mma16816_z(float& d0, float& d1, float& d2, float& d3,
                                           u32 a0, u32 a1, u32 a2, u32 a3,
                                           u32 b0, u32 b1) {
    const float z = 0.0f;
    asm volatile(
        "mma.sync.aligned.m16n8k16.row.col.f32.f16.f16.f32 "
        "{%0,%1,%2,%3},{%4,%5,%6,%7},{%8,%9},{%10,%10,%10,%10};"
        : "=f"(d0), "=f"(d1), "=f"(d2), "=f"(d3)
        : "r"(a0), "r"(a1), "r"(a2), "r"(a3), "r"(b0), "r"(b1), "f"(z));
}

// ---------------- main kernel: 8 seqs/warp, HMMA + movmatrix ----------------------
// G(128x8) = W_ext(128x48) H_ext(48x8); k-tile 2 (x,bias rank-2) issues FIRST so
// the h-critical path is only 2 serial HMMAs. x chunks double-buffered in smem.
// Scales folded into weights: 0.5 for i,f,o (sigma(v) = 0.5 + 0.5 tanh(v/2)).
__global__ __launch_bounds__(128)
void bilstm_mma_kernel(const float* __restrict__ x,
                       const int* __restrict__ lengths,
                       const float* __restrict__ w_ih,
                       const float* __restrict__ w_hh,
                       const float* __restrict__ b_ih,
                       const float* __restrict__ b_hh,
                       const float* __restrict__ fc_w,
                       const float* __restrict__ fc_b,
                       const float* __restrict__ fc2_w,
                       const float* __restrict__ fc2_b,
                       float* __restrict__ out)
{
    const int lane = threadIdx.x & 31;
    const int wid  = threadIdx.x >> 5;
    const int g4 = lane >> 2;        // 0..7
    const int tq = lane & 3;         // 0..3

    // per-warp x chunks: DOUBLE-buffered packed (x, 1.0) halves, 8 seqs x 32 steps
    __shared__ u32 xpsh[4][2][8 * 32];

    // ---- A fragments (weights), loaded once ----
    const float scl[4] = {0.5f, 0.5f, 1.0f, 0.5f};
    u32 Afr[8][2][4];
    u32 A2f[8][2];
#pragma unroll
    for (int mt = 0; mt < 8; ++mt) {
        const int g = mt >> 1, bb = mt & 1;
        const float s = scl[g];
        const int R0 = g * 32 + bb * 16 + g4;
        const int R1 = R0 + 8;
#pragma unroll
        for (int kt = 0; kt < 2; ++kt) {
            const int c0 = kt * 16 + 2 * tq;
            Afr[mt][kt][0] = f2h2(s * __ldg(w_hh + R0 * 32 + c0),
                                  s * __ldg(w_hh + R0 * 32 + c0 + 1));
            Afr[mt][kt][1] = f2h2(s * __ldg(w_hh + R1 * 32 + c0),
                                  s * __ldg(w_hh + R1 * 32 + c0 + 1));
            Afr[mt][kt][2] = f2h2(s * __ldg(w_hh + R0 * 32 + c0 + 8),
                                  s * __ldg(w_hh + R0 * 32 + c0 + 9));
            Afr[mt][kt][3] = f2h2(s * __ldg(w_hh + R1 * 32 + c0 + 8),
                                  s * __ldg(w_hh + R1 * 32 + c0 + 9));
        }
        if (tq == 0) {   // k-tile 2: col 32 = w_ih, col 33 = fused bias
            A2f[mt][0] = f2h2(s * __ldg(w_ih + R0),
                              s * (__ldg(b_ih + R0) + __ldg(b_hh + R0)));
            A2f[mt][1] = f2h2(s * __ldg(w_ih + R1),
                              s * (__ldg(b_ih + R1) + __ldg(b_hh + R1)));
        } else { A2f[mt][0] = 0u; A2f[mt][1] = 0u; }
    }

    const unsigned FULL = 0xffffffffu;

    // ---- persistent work queue over sorted 8-seq groups ----
    for (;;) {
        int s0 = 0;
        if (lane == 0) s0 = atomicAdd(&g_counter, 1);
        s0 = __shfl_sync(FULL, s0, 0);
        if (s0 >= NGROUPS) break;

        int idxs[8];
#pragma unroll
        for (int r = 0; r < 8; ++r) idxs[r] = g_order[s0 * 8 + r];
        const int lenmax = __ldg(lengths + idxs[0]);          // sorted desc
        const int lenA = __ldg(lengths + idxs[2 * tq]);       // seq 2tq
        const int lenB = __ldg(lengths + idxs[2 * tq + 1]);   // seq 2tq+1

        // states: st = bb*4 + rh*2 + sh -> seq 2tq+sh, hidden j = 16bb + g4 + 8rh
        float hS[8], cS[8];
#pragma unroll
        for (int st = 0; st < 8; ++st) { hS[st] = 0.0f; cS[st] = 0.0f; }

        const int tmax = lenmax - 1;
        const int ctop = tmax >> 5;

        // stage first chunk; prefetch second into registers
        int xb = 0;
        float pend[8];
#pragma unroll
        for (int r = 0; r < 8; ++r) {
            const float v = __ldg(x + (size_t)idxs[r] * T_SZ + (ctop << 5) + lane);
            xpsh[wid][0][r * 32 + lane] = f2h2(v, 1.0f);
            pend[r] = (ctop > 0)
                ? __ldg(x + (size_t)idxs[r] * T_SZ + ((ctop - 1) << 5) + lane) : 0.0f;
        }
        __syncwarp();

#pragma unroll 1
        for (int c = ctop; c >= 0; --c) {
            const u32* xpkS = xpsh[wid][xb];
            const int istart = (c == ctop) ? (tmax & 31) : 31;

#pragma unroll 2
            for (int i = istart; i >= 0; --i) {
                const int t = (c << 5) + i;
                const bool m0 = t < lenA;
                const bool m1 = t < lenB;

                const u32 xv  = xpkS[g4 * 32 + i];
                const u32 b20 = (tq == 0) ? xv : 0u;

                // B fragments: register-space transpose of h (no smem)
                const u32 b00 = movm_t(f2h2(hS[0], hS[1]));   // j 0..7
                const u32 b01 = movm_t(f2h2(hS[2], hS[3]));   // j 8..15
                const u32 b10 = movm_t(f2h2(hS[4], hS[5]));   // j 16..23
                const u32 b11 = movm_t(f2h2(hS[6], hS[7]));   // j 24..31

                float d[8][4];

                // kt2 FIRST (depends only on x -> off the h-critical path),
                // zero-C form kills accumulator init movs.
#pragma unroll
                for (int mt = 0; mt < 8; ++mt)
                    mma16816_z(d[mt][0], d[mt][1], d[mt][2], d[mt][3],
                               A2f[mt][0], A2f[mt][1], 0u, 0u, b20, 0u);

                // bb = 0 tiles: kt0, kt1 (h-dependent; 2 serial MMAs each)
#pragma unroll
                for (int mt = 0; mt < 8; mt += 2) {
                    mma16816(d[mt][0], d[mt][1], d[mt][2], d[mt][3],
                             Afr[mt][0][0], Afr[mt][0][1], Afr[mt][0][2], Afr[mt][0][3],
                             b00, b01);
                    mma16816(d[mt][0], d[mt][1], d[mt][2], d[mt][3],
                             Afr[mt][1][0], Afr[mt][1][1], Afr[mt][1][2], Afr[mt][1][3],
                             b10, b11);
                }

                // activate bb=0 states (overlaps bb=1 MMA issue below)
#pragma unroll
                for (int st = 0; st < 4; ++st) {
                    const int sh = st & 1, rh = (st >> 1) & 1;
                    const int dreg = 2 * rh + sh;
                    const float I = fmaf(0.5f, fast_tanh(d[0][dreg]), 0.5f);
                    const float F = fmaf(0.5f, fast_tanh(d[2][dreg]), 0.5f);
                    const float G = fast_tanh(d[4][dreg]);
                    const float O = fmaf(0.5f, fast_tanh(d[6][dreg]), 0.5f);
                    const float cn = fmaf(F, cS[st], I * G);
                    const float hn = O * fast_tanh(cn);
                    const bool m = (sh ? m1 : m0);
                    cS[st] = m ? cn : cS[st];
                    hS[st] = m ? hn : hS[st];
                }

                // bb = 1 tiles
#pragma unroll
                for (int mt = 1; mt < 8; mt += 2) {
                    mma16816(d[mt][0], d[mt][1], d[mt][2], d[mt][3],
                             Afr[mt][0][0], Afr[mt][0][1], Afr[mt][0][2], Afr[mt][0][3],
                             b00, b01);
                    mma16816(d[mt][0], d[mt][1], d[mt][2], d[mt][3],
                             Afr[mt][1][0], Afr[mt][1][1], Afr[mt][1][2], Afr[mt][1][3],
                             b10, b11);
                }

#pragma unroll
                for (int st = 4; st < 8; ++st) {
                    const int sh = st & 1, rh = (st >> 1) & 1;
                    const int dreg = 2 * rh + sh;
                    const float I = fmaf(0.5f, fast_tanh(d[1][dreg]), 0.5f);
                    const float F = fmaf(0.5f, fast_tanh(d[3][dreg]), 0.5f);
                    const float G = fast_tanh(d[5][dreg]);
                    const float O = fmaf(0.5f, fast_tanh(d[7][dreg]), 0.5f);
                    const float cn = fmaf(F, cS[st], I * G);
                    const float hn = O * fast_tanh(cn);
                    const bool m = (sh ? m1 : m0);
                    cS[st] = m ? cn : cS[st];
                    hS[st] = m ? hn : hS[st];
                }
            }

            // chunk boundary: publish prefetched chunk, start next prefetch
            if (c > 0) {
#pragma unroll
                for (int r = 0; r < 8; ++r) {
                    xpsh[wid][xb ^ 1][r * 32 + lane] = f2h2(pend[r], 1.0f);
                    pend[r] = (c > 1)
                        ? __ldg(x + (size_t)idxs[r] * T_SZ + ((c - 2) << 5) + lane)
                        : 0.0f;
                }
                __syncwarp();
                xb ^= 1;
            }
        }

        // ---- FC head: sigmoid(fc2(elu(fc1(h_n)))) for the 8 group sequences ----
        float* hf = reinterpret_cast<float*>(xpsh[wid][0]);   // reuse: hf[s*32+j]
        __syncwarp();
#pragma unroll
        for (int st = 0; st < 8; ++st) {
            const int sh = st & 1, rh = (st >> 1) & 1, bb = st >> 2;
            hf[(2 * tq + sh) * 32 + 16 * bb + g4 + 8 * rh] = hS[st];
        }
        __syncwarp();

#pragma unroll 1
        for (int s = 0; s < 8; ++s) {
            float o1 = __ldg(fc_b + lane);
            float o2 = __ldg(fc_b + lane + 32);
#pragma unroll
            for (int k = 0; k < 32; ++k) {
                const float hk = hf[s * 32 + k];
                o1 = fmaf(hk, __ldg(fc_w + lane * 32 + k), o1);
                o2 = fmaf(hk, __ldg(fc_w + (lane + 32) * 32 + k), o2);
            }
            o1 = (o1 > 0.0f) ? o1 : (fast_ex2(1.44269504f * o1) - 1.0f);
            o2 = (o2 > 0.0f) ? o2 : (fast_ex2(1.44269504f * o2) - 1.0f);
            float part = o1 * __ldg(fc2_w + lane) + o2 * __ldg(fc2_w + lane + 32);
#pragma unroll
            for (int dd = 16; dd >= 1; dd >>= 1)
                part += __shfl_xor_sync(FULL, part, dd);
            if (lane == 0)
                out[idxs[s]] = sigmoid_(part + __ldg(fc2_b));
        }
        __syncwarp();      // head reads done before next group's x staging
    }
}

extern "C" void kernel_launch(void* const* d_in, const int* in_sizes, int n_in,
                              void* d_out, int out_size)
{
    const float* x       = (const float*)d_in[0];
    const int*   lengths = (const int*)  d_in[1];
    const float* w_ih    = (const float*)d_in[2];
    const float* w_hh    = (const float*)d_in[3];
    const float* b_ih    = (const float*)d_in[4];
    const float* b_hh    = (const float*)d_in[5];
    const float* fc_w    = (const float*)d_in[6];
    const float* fc_b    = (const float*)d_in[7];
    const float* fc2_w   = (const float*)d_in[8];
    const float* fc2_b   = (const float*)d_in[9];
    float* out = (float*)d_out;

    sort_kernel<<<1, 1024>>>(lengths);
    // 148 blocks x 4 warps = 1 warp/SMSP; atomic queue over 512 LPT-sorted
    // 8-seq groups (592 warps > 512 groups: each warp runs at most one).
    bilstm_mma_kernel<<<148, 128>>>(x, lengths, w_ih, w_hh, b_ih, b_hh,
                                    fc_w, fc_b, fc2_w, fc2_b, out);
}

// round 17
// speedup vs baseline: 1.9104x; 1.1550x over previous
#include <cuda_runtime.h>
#include <cuda_fp16.h>

#define B_SZ 4096
#define T_SZ 2048
#define NGROUPS 512
typedef unsigned u32;

__device__ int g_order[B_SZ];

// ---------------- prologue: counting sort by descending length --------------------
__global__ __launch_bounds__(1024)
void sort_kernel(const int* __restrict__ lengths)
{
    __shared__ int hist[2048];
    const int tid = threadIdx.x;
    hist[tid] = 0; hist[tid + 1024] = 0;
    __syncthreads();
    for (int i = tid; i < B_SZ; i += 1024)
        atomicAdd(&hist[T_SZ - lengths[i]], 1);
    __syncthreads();
    const int o0 = hist[tid], o1 = hist[tid + 1024];
    for (int off = 1; off < 2048; off <<= 1) {
        int v0 = hist[tid]        + ((tid        >= off) ? hist[tid - off]        : 0);
        int v1 = hist[tid + 1024] + ((tid + 1024 >= off) ? hist[tid + 1024 - off] : 0);
        __syncthreads();
        hist[tid] = v0; hist[tid + 1024] = v1;
        __syncthreads();
    }
    hist[tid] -= o0; hist[tid + 1024] -= o1;
    __syncthreads();
    for (int i = tid; i < B_SZ; i += 1024) {
        int pos = atomicAdd(&hist[T_SZ - lengths[i]], 1);
        g_order[pos] = i;
    }
}

// ---------------- helpers ---------------------------------------------------------
__device__ __forceinline__ float fast_ex2(float x) {
    float r; asm("ex2.approx.f32 %0, %1;" : "=f"(r) : "f"(x)); return r;
}
__device__ __forceinline__ float fast_rcp(float x) {
    float r; asm("rcp.approx.f32 %0, %1;" : "=f"(r) : "f"(x)); return r;
}
__device__ __forceinline__ float fast_tanh(float x) {
    float r; asm("tanh.approx.f32 %0, %1;" : "=f"(r) : "f"(x)); return r;
}
__device__ __forceinline__ float sigmoid_(float x) {
    return fast_rcp(1.0f + fast_ex2(-1.44269504f * x));
}
__device__ __forceinline__ u32 f2h2(float lo, float hi) {
    __half2 h = __floats2half2_rn(lo, hi);             // .x = lo, .y = hi
    return *reinterpret_cast<u32*>(&h);
}
__device__ __forceinline__ u32 movm_t(u32 a) {         // 8x8 b16 register transpose
    u32 d; asm("movmatrix.sync.aligned.m8n8.trans.b16 %0, %1;" : "=r"(d) : "r"(a));
    return d;
}
// D += A(16x16 f16,row) * B(16x8 f16,col)   (fp32 accum)
__device__ __forceinline__ void mma16816(float& d0, float& d1, float& d2, float& d3,
                                         u32 a0, u32 a1, u32 a2, u32 a3,
                                         u32 b0, u32 b1) {
    asm volatile(
        "mma.sync.aligned.m16n8k16.row.col.f32.f16.f16.f32 "
        "{%0,%1,%2,%3},{%4,%5,%6,%7},{%8,%9},{%0,%1,%2,%3};"
        : "+f"(d0), "+f"(d1), "+f"(d2), "+f"(d3)
        : "r"(a0), "r"(a1), "r"(a2), "r"(a3), "r"(b0), "r"(b1));
}
// D = A*B + 0 : zero C operand (no accumulator init movs)
__device__ __forceinline__ void mma16816_z(float& d0, float& d1, float& d2, float& d3,
                                           u32 a0, u32 a1, u32 a2, u32 a3,
                                           u32 b0, u32 b1) {
    const float z = 0.0f;
    asm volatile(
        "mma.sync.aligned.m16n8k16.row.col.f32.f16.f16.f32 "
        "{%0,%1,%2,%3},{%4,%5,%6,%7},{%8,%9},{%10,%10,%10,%10};"
        : "=f"(d0), "=f"(d1), "=f"(d2), "=f"(d3)
        : "r"(a0), "r"(a1), "r"(a2), "r"(a3), "r"(b0), "r"(b1), "f"(z));
}
#define BARP(id) asm volatile("bar.sync %0, %1;" :: "r"(id), "r"(64) : "memory")

// ---------------- main kernel: 8 seqs per WARP-PAIR, split by hidden half ---------
// Pair = 2 warps. Warp bb owns hidden j in [16bb, 16bb+16): 4 gate m-tiles
// (12 MMAs) and 4 states/lane (20 MUFU). Full h rebuilt per step: own half from
// registers, other half via double-buffered smem exchange + named barrier.
// Scales folded into weights: 0.5 for i,f,o (sigma(v) = 0.5 + 0.5 tanh(v/2)).
__global__ __launch_bounds__(256)
void bilstm_mma_kernel(const float* __restrict__ x,
                       const int* __restrict__ lengths,
                       const float* __restrict__ w_ih,
                       const float* __restrict__ w_hh,
                       const float* __restrict__ b_ih,
                       const float* __restrict__ b_hh,
                       const float* __restrict__ fc_w,
                       const float* __restrict__ fc_b,
                       const float* __restrict__ fc2_w,
                       const float* __restrict__ fc2_b,
                       float* __restrict__ out)
{
    const int lane = threadIdx.x & 31;
    const int wid  = threadIdx.x >> 5;       // 0..7
    const int pr   = wid >> 1;               // pair 0..3
    const int bb   = wid & 1;                // hidden half
    const int g4 = lane >> 2;                // 0..7
    const int tq = lane & 3;                 // 0..3
    const int barid = pr + 1;

    __shared__ u32  xps[4][256];             // per-pair packed (x,1): [r*32+lane]
    __shared__ uint2 hx[4][2][2][32];        // [pair][buf][bb][lane] h-half packs

    // group: interleave so each block mixes length quartiles
    const int group = pr * 128 + blockIdx.x;

    // ---- A fragments for OUR hidden half (4 gate tiles) ----
    const float scl[4] = {0.5f, 0.5f, 1.0f, 0.5f};
    u32 Afr[4][2][4];
    u32 A2f[4][2];
#pragma unroll
    for (int g = 0; g < 4; ++g) {
        const float s = scl[g];
        const int R0 = g * 32 + bb * 16 + g4;
        const int R1 = R0 + 8;
#pragma unroll
        for (int kt = 0; kt < 2; ++kt) {
            const int c0 = kt * 16 + 2 * tq;
            Afr[g][kt][0] = f2h2(s * __ldg(w_hh + R0 * 32 + c0),
                                 s * __ldg(w_hh + R0 * 32 + c0 + 1));
            Afr[g][kt][1] = f2h2(s * __ldg(w_hh + R1 * 32 + c0),
                                 s * __ldg(w_hh + R1 * 32 + c0 + 1));
            Afr[g][kt][2] = f2h2(s * __ldg(w_hh + R0 * 32 + c0 + 8),
                                 s * __ldg(w_hh + R0 * 32 + c0 + 9));
            Afr[g][kt][3] = f2h2(s * __ldg(w_hh + R1 * 32 + c0 + 8),
                                 s * __ldg(w_hh + R1 * 32 + c0 + 9));
        }
        if (tq == 0) {
            A2f[g][0] = f2h2(s * __ldg(w_ih + R0),
                             s * (__ldg(b_ih + R0) + __ldg(b_hh + R0)));
            A2f[g][1] = f2h2(s * __ldg(w_ih + R1),
                             s * (__ldg(b_ih + R1) + __ldg(b_hh + R1)));
        } else { A2f[g][0] = 0u; A2f[g][1] = 0u; }
    }

    int idxs[8];
#pragma unroll
    for (int r = 0; r < 8; ++r) idxs[r] = g_order[group * 8 + r];
    const int lenmax = __ldg(lengths + idxs[0]);            // sorted desc
    const int lenA = __ldg(lengths + idxs[2 * tq]);         // seq 2tq
    const int lenB = __ldg(lengths + idxs[2 * tq + 1]);     // seq 2tq+1

    // states: st = rh*2 + sh -> seq 2tq+sh, hidden j = 16bb + g4 + 8rh
    float hS[4], cS[4];
#pragma unroll
    for (int st = 0; st < 4; ++st) { hS[st] = 0.0f; cS[st] = 0.0f; }
    u32 pk0 = 0u, pk1 = 0u;                  // own h packs (rh=0, rh=1)

    hx[pr][0][bb][lane] = make_uint2(0u, 0u);
    hx[pr][1][bb][lane] = make_uint2(0u, 0u);
    __syncthreads();

    const int tmax = lenmax - 1;
    const int ctop = tmax >> 5;

    // stage first chunk (each warp stages its 4 seq rows); prefetch second
    float pend[4];
#pragma unroll
    for (int rr = 0; rr < 4; ++rr) {
        const int r = 4 * bb + rr;
        const float v = __ldg(x + (size_t)idxs[r] * T_SZ + (ctop << 5) + lane);
        xps[pr][r * 32 + lane] = f2h2(v, 1.0f);
        pend[rr] = (ctop > 0)
            ? __ldg(x + (size_t)idxs[r] * T_SZ + ((ctop - 1) << 5) + lane) : 0.0f;
    }
    BARP(barid);

    int buf = 0;
#pragma unroll 1
    for (int c = ctop; c >= 0; --c) {
        const int istart = (c == ctop) ? (tmax & 31) : 31;

#pragma unroll 2
        for (int i = istart; i >= 0; --i) {
            const int t = (c << 5) + i;
            const bool m0 = t < lenA;
            const bool m1 = t < lenB;

            const u32 xv  = xps[pr][g4 * 32 + i];
            const u32 b20 = (tq == 0) ? xv : 0u;

            // full h: own half from regs, other half from smem (prev step's bar)
            const uint2 oth = hx[pr][buf][bb ^ 1][lane];    // LDS.64
            const u32 bs0 = movm_t(pk0), bs1 = movm_t(pk1);
            const u32 bo0 = movm_t(oth.x), bo1 = movm_t(oth.y);
            const u32 b00 = bb ? bo0 : bs0;                  // j 0..7
            const u32 b01 = bb ? bo1 : bs1;                  // j 8..15
            const u32 b10 = bb ? bs0 : bo0;                  // j 16..23
            const u32 b11 = bb ? bs1 : bo1;                  // j 24..31

            float d[4][4];
            // kt2 (x,bias) first: off the h-critical path, zero-C form
#pragma unroll
            for (int g = 0; g < 4; ++g)
                mma16816_z(d[g][0], d[g][1], d[g][2], d[g][3],
                           A2f[g][0], A2f[g][1], 0u, 0u, b20, 0u);
#pragma unroll
            for (int g = 0; g < 4; ++g) {
                mma16816(d[g][0], d[g][1], d[g][2], d[g][3],
                         Afr[g][0][0], Afr[g][0][1], Afr[g][0][2], Afr[g][0][3],
                         b00, b01);
                mma16816(d[g][0], d[g][1], d[g][2], d[g][3],
                         Afr[g][1][0], Afr[g][1][1], Afr[g][1][2], Afr[g][1][3],
                         b10, b11);
            }

            // activations: 4 states/lane (d[0]=i, d[1]=f, d[2]=g, d[3]=o)
#pragma unroll
            for (int st = 0; st < 4; ++st) {
                const int sh = st & 1, rh = st >> 1;
                const int dreg = 2 * rh + sh;
                const float I = fmaf(0.5f, fast_tanh(d[0][dreg]), 0.5f);
                const float F = fmaf(0.5f, fast_tanh(d[1][dreg]), 0.5f);
                const float G = fast_tanh(d[2][dreg]);
                const float O = fmaf(0.5f, fast_tanh(d[3][dreg]), 0.5f);
                const float cn = fmaf(F, cS[st], I * G);
                const float hn = O * fast_tanh(cn);
                const bool m = sh ? m1 : m0;
                cS[st] = m ? cn : cS[st];
                hS[st] = m ? hn : hS[st];
            }

            // publish new half for partner; keep own packs in regs
            pk0 = f2h2(hS[0], hS[1]);
            pk1 = f2h2(hS[2], hS[3]);
            hx[pr][buf ^ 1][bb][lane] = make_uint2(pk0, pk1);  // STS.64
            BARP(barid);
            buf ^= 1;
        }

        // chunk boundary: last read of old chunk was before the step's bar
        if (c > 0) {
#pragma unroll
            for (int rr = 0; rr < 4; ++rr) {
                const int r = 4 * bb + rr;
                xps[pr][r * 32 + lane] = f2h2(pend[rr], 1.0f);
                pend[rr] = (c > 1)
                    ? __ldg(x + (size_t)idxs[r] * T_SZ + ((c - 2) << 5) + lane)
                    : 0.0f;
            }
            BARP(barid);
        }
    }

    // ---- FC head: sigmoid(fc2(elu(fc1(h_n)))); each warp does 4 seqs ----
    float* hf = reinterpret_cast<float*>(xps[pr]);    // 256 floats: hf[s*32+j]
#pragma unroll
    for (int st = 0; st < 4; ++st) {
        const int sh = st & 1, rh = st >> 1;
        hf[(2 * tq + sh) * 32 + 16 * bb + g4 + 8 * rh] = hS[st];
    }
    BARP(barid);

#pragma unroll 1
    for (int ss = 0; ss < 4; ++ss) {
        const int s = 4 * bb + ss;
        float o1 = __ldg(fc_b + lane);
        float o2 = __ldg(fc_b + lane + 32);
#pragma unroll
        for (int k = 0; k < 32; ++k) {
            const float hk = hf[s * 32 + k];
            o1 = fmaf(hk, __ldg(fc_w + lane * 32 + k), o1);
            o2 = fmaf(hk, __ldg(fc_w + (lane + 32) * 32 + k), o2);
        }
        o1 = (o1 > 0.0f) ? o1 : (fast_ex2(1.44269504f * o1) - 1.0f);
        o2 = (o2 > 0.0f) ? o2 : (fast_ex2(1.44269504f * o2) - 1.0f);
        float part = o1 * __ldg(fc2_w + lane) + o2 * __ldg(fc2_w + lane + 32);
#pragma unroll
        for (int dd = 16; dd >= 1; dd >>= 1)
            part += __shfl_xor_sync(0xffffffffu, part, dd);
        if (lane == 0)
            out[idxs[s]] = sigmoid_(part + __ldg(fc2_b));
    }
}

extern "C" void kernel_launch(void* const* d_in, const int* in_sizes, int n_in,
                              void* d_out, int out_size)
{
    const float* x       = (const float*)d_in[0];
    const int*   lengths = (const int*)  d_in[1];
    const float* w_ih    = (const float*)d_in[2];
    const float* w_hh    = (const float*)d_in[3];
    const float* b_ih    = (const float*)d_in[4];
    const float* b_hh    = (const float*)d_in[5];
    const float* fc_w    = (const float*)d_in[6];
    const float* fc_b    = (const float*)d_in[7];
    const float* fc2_w   = (const float*)d_in[8];
    const float* fc2_b   = (const float*)d_in[9];
    float* out = (float*)d_out;

    sort_kernel<<<1, 1024>>>(lengths);
    // 128 blocks x 8 warps = 512 warp-pairs, one 8-seq group each (static).
    // Pair p of block b -> group p*128+b: quartile-interleaved across blocks.
    bilstm_mma_kernel<<<128, 256>>>(x, lengths, w_ih, w_hh, b_ih, b_hh,
                                    fc_w, fc_b, fc2_w, fc2_b, out);
}